// round 14
// baseline (speedup 1.0000x reference)
#include <cuda_runtime.h>
#include <cuda_bf16.h>
#include <cuda_fp16.h>
#include <cstdint>
#include <math.h>

// Problem constants (match reference)
#define K_NUM    131072
#define IN_NUM_  50000
#define OUT_NUM_ 50000
#define FEAT_    128
#define NPTS     16
#define ADD_     12
#define EPS_     1e-7f

// Per-output-row bucket capacity (Poisson(<=8.4) peak; overflow list guards).
#define CAP      40
#define OVF_CAP  65536

// ---------------------------------------------------------------------------
// Bit-exact sigmoid path (DO NOT TOUCH — verified rel_err 3.2e-7 R10-R13).
// Cephes-classic f32 exp as XLA:CPU emits on aarch64 NEON (FMA pmadd).
// Needed ONLY for m0/m1 (discrete floor/ceil sensitivity).
// ---------------------------------------------------------------------------
__device__ __forceinline__ float cephes_expf_fma(float x) {
    const float LOG2EF = 1.44269504088896341f;
    const float C1     = 0.693359375f;
    const float C2     = -2.12194440e-4f;

    float fx = __fmaf_rn(x, LOG2EF, 0.5f);
    fx = floorf(fx);

    const float tmp = __fmul_rn(fx, C1);
    const float z   = __fmul_rn(fx, C2);
    float xr = __fsub_rn(x, tmp);
    xr = __fsub_rn(xr, z);

    const float zz = __fmul_rn(xr, xr);

    float y =             1.9875691500e-4f;
    y = __fmaf_rn(y, xr,  1.3981999507e-3f);
    y = __fmaf_rn(y, xr,  8.3334519073e-3f);
    y = __fmaf_rn(y, xr,  4.1665795894e-2f);
    y = __fmaf_rn(y, xr,  1.6666665459e-1f);
    y = __fmaf_rn(y, xr,  5.0000001201e-1f);
    y = __fmaf_rn(y, zz,  xr);
    y = __fadd_rn(y, 1.0f);

    const int n = (int)fx;
    const float p2n = __int_as_float((n + 127) << 23);
    return __fmul_rn(y, p2n);
}

__device__ __forceinline__ float sigmoid_ref(float v) {
    const float e = cephes_expf_fma(-v);
    return __fdiv_rn(1.0f, __fadd_rn(1.0f, e));
}

// Smooth-path sigmoid (value): plain expf is ample (weights are smooth).
__device__ __forceinline__ float sigmoid_fast(float v) {
    return 1.0f / (1.0f + expf(-v));
}

// fp32 softplus (sigma sensitivity ~1e-5 << tolerance; verified R12/R13).
__device__ __forceinline__ float softplus_f32(float v) {
    return fmaxf(v, 0.0f) + log1pf(expf(-fabsf(v)));
}

// ---------------------------------------------------------------------------
// Scratch (static __device__ arrays — no allocation)
// ---------------------------------------------------------------------------
__device__ int    g_cnt[OUT_NUM_];
__device__ float4 g_entry[(size_t)OUT_NUM_ * CAP];   // 25.6 MB
__device__ int    g_ovf_cnt;
__device__ float4 g_ovf[OVF_CAP];
__device__ __half g_xh[(size_t)IN_NUM_ * FEAT_];     // fp16 copy of x, 12.8 MB

__device__ __forceinline__ void push_entry(int row, int j0, int j1,
                                           float w0, float w1) {
    const int pos = atomicAdd(&g_cnt[row], 1);
    if (pos < CAP) {
        g_entry[(size_t)row * CAP + pos] =
            make_float4(__int_as_float(j0), __int_as_float(j1), w0, w1);
    } else {
        int op = atomicAdd(&g_ovf_cnt, 1);
        if (op < OVF_CAP)
            g_ovf[op] = make_float4(__int_as_float(row), __int_as_float(j0), w0, 0.0f);
        if (w1 != 0.0f) {
            op = atomicAdd(&g_ovf_cnt, 1);
            if (op < OVF_CAP)
                g_ovf[op] = make_float4(__int_as_float(row), __int_as_float(j1), w1, 0.0f);
        }
    }
}

// ---------------------------------------------------------------------------
// Kernel P: fp32 -> fp16 copy of x (one float4 -> two half2 per thread)
// ---------------------------------------------------------------------------
__global__ void __launch_bounds__(256)
convert_x_kernel(const float* __restrict__ x)
{
    const int idx = blockIdx.x * blockDim.x + threadIdx.x;   // float4 index
    const int total = (IN_NUM_ * FEAT_) / 4;
    if (idx >= total) return;
    const float4 v = __ldg((const float4*)x + idx);
    __half2* dst = (__half2*)(g_xh + (size_t)idx * 4);
    dst[0] = __floats2half2_rn(v.x, v.y);
    dst[1] = __floats2half2_rn(v.z, v.w);
}

// ---------------------------------------------------------------------------
// Kernel A: per-edge weight computation + bucket append (1 thread / edge)
// ---------------------------------------------------------------------------
__global__ void __launch_bounds__(128)
compute_weights_kernel(const float* __restrict__ params,
                       const int*   __restrict__ sampled)
{
    const int k = blockIdx.x * blockDim.x + threadIdx.x;
    if (k >= K_NUM) return;

    const float4 p = __ldg((const float4*)params + k);

    // Bit-exact sigmoids for means (discrete); fast for value (smooth).
    const float m0 = __fmul_rn(sigmoid_ref(p.x), (float)(OUT_NUM_ - 1));
    const float m1 = __fmul_rn(sigmoid_ref(p.y), (float)(IN_NUM_ - 1));
    const float sp    = softplus_f32(__fadd_rn(p.z, 2.0f));
    const float sigma = __fmul_rn(__fmul_rn(__fadd_rn(sp, EPS_),
                                            (float)OUT_NUM_), 0.2f);
    const float inv_var = __fdiv_rn(1.0f, __fadd_rn(EPS_, sigma));
    const float value   = sigmoid_fast(p.w);

    const float f0 = floorf(m0), c0 = ceilf(m0);
    const float f1 = floorf(m1), c1 = ceilf(m1);

    int   pi[NPTS], pj[NPTS];
    float prop[NPTS];

    // Neighbor order matches FLOOR_MASK: (T,T),(T,F),(F,T),(F,F), True->floor
    pi[0] = (int)f0; pj[0] = (int)f1;
    pi[1] = (int)f0; pj[1] = (int)c1;
    pi[2] = (int)c0; pj[2] = (int)f1;
    pi[3] = (int)c0; pj[3] = (int)c1;

    const int4* sp4 = (const int4*)(sampled + (size_t)k * (ADD_ * 2));
    #pragma unroll
    for (int q = 0; q < 6; q++) {
        const int4 v = __ldg(sp4 + q);
        pi[4 + q * 2]     = v.x;  pj[4 + q * 2]     = v.y;
        pi[4 + q * 2 + 1] = v.z;  pj[4 + q * 2 + 1] = v.w;
    }

    // Neighbor props: arg in [-2.1e-3, 0] -> quadratic exp (err ~1.4e-9).
    #pragma unroll
    for (int t = 0; t < 4; t++) {
        const float di = (float)pi[t] - m0;
        const float dj = (float)pj[t] - m1;
        const float arg = -0.5f * (di * di + dj * dj) * inv_var;
        prop[t] = 1.0f + arg * (1.0f + 0.5f * arg);
    }
    // Sampled props: expf underflows to exactly 0 below ~-103.97 (skip).
    #pragma unroll
    for (int t = 4; t < NPTS; t++) {
        const float di = (float)pi[t] - m0;
        const float dj = (float)pj[t] - m1;
        const float arg = -0.5f * (di * di + dj * dj) * inv_var;
        prop[t] = (arg < -104.0f) ? 0.0f : expf(arg);
    }

    float denom = 0.0f;
    #pragma unroll
    for (int t = 0; t < NPTS; t++)
        denom = __fadd_rn(denom, __fadd_rn(prop[t], EPS_));
    const float scale = __fdiv_rn(value, denom);

    // Fused neighbor records: row i0 gets (w00,w01), row i1 gets (w10,w11)
    const int i0 = pi[0], i1 = pi[2], j0 = pj[0], j1 = pj[1];
    push_entry(i0, j0, j1, prop[0] * scale, prop[1] * scale);
    push_entry(i1, j0, j1, prop[2] * scale, prop[3] * scale);

    // Nonzero sampled points (~0.4%): single-input records (w1 = 0)
    #pragma unroll
    for (int t = 4; t < NPTS; t++) {
        if (prop[t] != 0.0f)
            push_entry(pi[t], pj[t], pj[t], prop[t] * scale, 0.0f);
    }
}

// ---------------------------------------------------------------------------
// Kernel B: one warp per output row — fp16 gathers (256B/row), fp32
// accumulate, single plain STG per row. No atomics, no output memset.
// ---------------------------------------------------------------------------
__device__ __forceinline__ void acc_row_h(int j, float w, int lane,
                                          float& ax, float& ay,
                                          float& az, float& aw) {
    // 4 halves per lane: 8 bytes -> 256 B per row across the warp
    const uint2 rv = __ldg((const uint2*)(g_xh + (size_t)j * FEAT_) + lane);
    const float2 lo = __half22float2(*(const __half2*)&rv.x);
    const float2 hi = __half22float2(*(const __half2*)&rv.y);
    ax = fmaf(w, lo.x, ax);
    ay = fmaf(w, lo.y, ay);
    az = fmaf(w, hi.x, az);
    aw = fmaf(w, hi.y, aw);
}

__global__ void __launch_bounds__(256)
row_scatter_kernel(float* __restrict__ out)
{
    const int row  = (blockIdx.x * blockDim.x + threadIdx.x) >> 5;
    const int lane = threadIdx.x & 31;
    if (row >= OUT_NUM_) return;

    const int n = min(g_cnt[row], CAP);
    const float4* base = g_entry + (size_t)row * CAP;

    float ax = 0.0f, ay = 0.0f, az = 0.0f, aw = 0.0f;

    if (n > 0) {
        float4 rec = base[0];                       // warp-broadcast load
        for (int e = 0; e < n; e++) {
            const float4 nxt = (e + 1 < n) ? base[e + 1] : rec;  // prefetch
            acc_row_h(__float_as_int(rec.x), rec.z, lane, ax, ay, az, aw);
            if (rec.w != 0.0f)                      // warp-uniform branch
                acc_row_h(__float_as_int(rec.y), rec.w, lane, ax, ay, az, aw);
            rec = nxt;
        }
    }

    // lane covers feats [lane*4, lane*4+4)
    ((float4*)(out + (size_t)row * FEAT_))[lane] = make_float4(ax, ay, az, aw);
}

// ---------------------------------------------------------------------------
// Kernel C: overflow entries (normally zero) — atomic red after the STG pass.
// ---------------------------------------------------------------------------
__global__ void __launch_bounds__(256)
overflow_kernel(float* __restrict__ out)
{
    const int warp   = (blockIdx.x * blockDim.x + threadIdx.x) >> 5;
    const int lane   = threadIdx.x & 31;
    const int nwarps = (gridDim.x * blockDim.x) >> 5;
    const int cnt    = min(g_ovf_cnt, OVF_CAP);

    for (int e = warp; e < cnt; e += nwarps) {
        const float4 rec = g_ovf[e];
        const int i = __float_as_int(rec.x);
        const int j = __float_as_int(rec.y);
        const float w = rec.z;
        float ax = 0, ay = 0, az = 0, aw = 0;
        acc_row_h(j, w, lane, ax, ay, az, aw);
        float* dst = out + (size_t)i * FEAT_ + lane * 4;
        asm volatile("red.global.add.v4.f32 [%0], {%1,%2,%3,%4};"
                     :: "l"(dst), "f"(ax), "f"(ay), "f"(az), "f"(aw)
                     : "memory");
    }
}

extern "C" void kernel_launch(void* const* d_in, const int* in_sizes, int n_in,
                              void* d_out, int out_size) {
    const float* params  = (const float*)d_in[0];   // (K, 4)
    const float* x       = (const float*)d_in[1];   // (IN_NUM, 128)
    const int*   sampled = (const int*)  d_in[2];   // (K, 12, 2)
    float*       out     = (float*)d_out;           // (OUT_NUM, 128)

    // Zero bucket counters + overflow counter (no output memset needed).
    void* cnt_addr = nullptr;
    cudaGetSymbolAddress(&cnt_addr, g_cnt);
    cudaMemsetAsync(cnt_addr, 0, OUT_NUM_ * sizeof(int));
    void* ovf_addr = nullptr;
    cudaGetSymbolAddress(&ovf_addr, g_ovf_cnt);
    cudaMemsetAsync(ovf_addr, 0, sizeof(int));

    convert_x_kernel<<<(IN_NUM_ * FEAT_ / 4 + 255) / 256, 256>>>(x);
    compute_weights_kernel<<<(K_NUM + 127) / 128, 128>>>(params, sampled);
    row_scatter_kernel<<<(OUT_NUM_ * 32 + 255) / 256, 256>>>(out);
    overflow_kernel<<<16, 256>>>(out);
}

// round 15
// speedup vs baseline: 1.1438x; 1.1438x over previous
#include <cuda_runtime.h>
#include <cuda_bf16.h>
#include <cuda_fp16.h>
#include <cstdint>
#include <math.h>

// Problem constants (match reference)
#define K_NUM    131072
#define IN_NUM_  50000
#define OUT_NUM_ 50000
#define FEAT_    128
#define NPTS     16
#define ADD_     12
#define EPS_     1e-7f

// Per-output-row bucket capacity (Poisson(<=8.4) peak; overflow path guards).
#define CAP      40
#define OVF_CAP  65536

// Fused kernel block split
#define CONV_BLOCKS  ((IN_NUM_ * FEAT_ / 4 + 255) / 256)   // 6250
#define WT_BLOCKS    ((K_NUM + 255) / 256)                 // 512

// ---------------------------------------------------------------------------
// Bit-exact sigmoid path (DO NOT TOUCH — verified R10-R14).
// Cephes-classic f32 exp as XLA:CPU emits on aarch64 NEON (FMA pmadd).
// Needed ONLY for m0/m1 (discrete floor/ceil sensitivity).
// ---------------------------------------------------------------------------
__device__ __forceinline__ float cephes_expf_fma(float x) {
    const float LOG2EF = 1.44269504088896341f;
    const float C1     = 0.693359375f;
    const float C2     = -2.12194440e-4f;

    float fx = __fmaf_rn(x, LOG2EF, 0.5f);
    fx = floorf(fx);

    const float tmp = __fmul_rn(fx, C1);
    const float z   = __fmul_rn(fx, C2);
    float xr = __fsub_rn(x, tmp);
    xr = __fsub_rn(xr, z);

    const float zz = __fmul_rn(xr, xr);

    float y =             1.9875691500e-4f;
    y = __fmaf_rn(y, xr,  1.3981999507e-3f);
    y = __fmaf_rn(y, xr,  8.3334519073e-3f);
    y = __fmaf_rn(y, xr,  4.1665795894e-2f);
    y = __fmaf_rn(y, xr,  1.6666665459e-1f);
    y = __fmaf_rn(y, xr,  5.0000001201e-1f);
    y = __fmaf_rn(y, zz,  xr);
    y = __fadd_rn(y, 1.0f);

    const int n = (int)fx;
    const float p2n = __int_as_float((n + 127) << 23);
    return __fmul_rn(y, p2n);
}

__device__ __forceinline__ float sigmoid_ref(float v) {
    const float e = cephes_expf_fma(-v);
    return __fdiv_rn(1.0f, __fadd_rn(1.0f, e));
}

// Smooth-path sigmoid (value) — plain expf ample.
__device__ __forceinline__ float sigmoid_fast(float v) {
    return 1.0f / (1.0f + expf(-v));
}

// fp32 softplus (sigma sensitivity ~1e-5 << tolerance; verified R12+).
__device__ __forceinline__ float softplus_f32(float v) {
    return fmaxf(v, 0.0f) + log1pf(expf(-fabsf(v)));
}

// ---------------------------------------------------------------------------
// Scratch (static __device__ arrays — no allocation)
// g_cnt[OUT_NUM_] is the overflow counter -> single memset covers both.
// ---------------------------------------------------------------------------
__device__ int    g_cnt[OUT_NUM_ + 1];
__device__ float4 g_entry[(size_t)OUT_NUM_ * CAP];   // 25.6 MB
__device__ float4 g_ovf[OVF_CAP];                    // (row, j, w, 0) as_float
__device__ __half g_xh[(size_t)IN_NUM_ * FEAT_];     // fp16 copy of x, 12.8 MB

__device__ __forceinline__ void push_entry(int row, int j0, int j1,
                                           float w0, float w1) {
    const int pos = atomicAdd(&g_cnt[row], 1);
    if (pos < CAP) {
        g_entry[(size_t)row * CAP + pos] =
            make_float4(__int_as_float(j0), __int_as_float(j1), w0, w1);
    } else {
        int op = atomicAdd(&g_cnt[OUT_NUM_], 1);
        if (op < OVF_CAP)
            g_ovf[op] = make_float4(__int_as_float(row), __int_as_float(j0), w0, 0.0f);
        if (w1 != 0.0f) {
            op = atomicAdd(&g_cnt[OUT_NUM_], 1);
            if (op < OVF_CAP)
                g_ovf[op] = make_float4(__int_as_float(row), __int_as_float(j1), w1, 0.0f);
        }
    }
}

// ---------------------------------------------------------------------------
// Weight computation body (1 thread / edge)
// ---------------------------------------------------------------------------
__device__ __forceinline__ void compute_edge(int k,
                                             const float* __restrict__ params,
                                             const int*   __restrict__ sampled) {
    const float4 p = __ldg((const float4*)params + k);

    // Bit-exact sigmoids for means (discrete); fast for value (smooth).
    const float m0 = __fmul_rn(sigmoid_ref(p.x), (float)(OUT_NUM_ - 1));
    const float m1 = __fmul_rn(sigmoid_ref(p.y), (float)(IN_NUM_ - 1));
    const float sp    = softplus_f32(__fadd_rn(p.z, 2.0f));
    const float sigma = __fmul_rn(__fmul_rn(__fadd_rn(sp, EPS_),
                                            (float)OUT_NUM_), 0.2f);
    const float inv_var = __fdiv_rn(1.0f, __fadd_rn(EPS_, sigma));
    const float value   = sigmoid_fast(p.w);

    const float f0 = floorf(m0), c0 = ceilf(m0);
    const float f1 = floorf(m1), c1 = ceilf(m1);

    int   pi[NPTS], pj[NPTS];
    float prop[NPTS];

    // Neighbor order matches FLOOR_MASK: (T,T),(T,F),(F,T),(F,F), True->floor
    pi[0] = (int)f0; pj[0] = (int)f1;
    pi[1] = (int)f0; pj[1] = (int)c1;
    pi[2] = (int)c0; pj[2] = (int)f1;
    pi[3] = (int)c0; pj[3] = (int)c1;

    const int4* sp4 = (const int4*)(sampled + (size_t)k * (ADD_ * 2));
    #pragma unroll
    for (int q = 0; q < 6; q++) {
        const int4 v = __ldg(sp4 + q);
        pi[4 + q * 2]     = v.x;  pj[4 + q * 2]     = v.y;
        pi[4 + q * 2 + 1] = v.z;  pj[4 + q * 2 + 1] = v.w;
    }

    // Neighbor props: arg in [-2.1e-3, 0] -> quadratic exp (err ~1.4e-9).
    #pragma unroll
    for (int t = 0; t < 4; t++) {
        const float di = (float)pi[t] - m0;
        const float dj = (float)pj[t] - m1;
        const float arg = -0.5f * (di * di + dj * dj) * inv_var;
        prop[t] = 1.0f + arg * (1.0f + 0.5f * arg);
    }
    // Sampled props: expf underflows to exactly 0 below ~-103.97 (skip).
    #pragma unroll
    for (int t = 4; t < NPTS; t++) {
        const float di = (float)pi[t] - m0;
        const float dj = (float)pj[t] - m1;
        const float arg = -0.5f * (di * di + dj * dj) * inv_var;
        prop[t] = (arg < -104.0f) ? 0.0f : expf(arg);
    }

    float denom = 0.0f;
    #pragma unroll
    for (int t = 0; t < NPTS; t++)
        denom = __fadd_rn(denom, __fadd_rn(prop[t], EPS_));
    const float scale = __fdiv_rn(value, denom);

    // Fused neighbor records: row i0 gets (w00,w01), row i1 gets (w10,w11)
    const int i0 = pi[0], i1 = pi[2], j0 = pj[0], j1 = pj[1];
    push_entry(i0, j0, j1, prop[0] * scale, prop[1] * scale);
    push_entry(i1, j0, j1, prop[2] * scale, prop[3] * scale);

    // Nonzero sampled points (~0.4%): single-input records (w1 = 0)
    #pragma unroll
    for (int t = 4; t < NPTS; t++) {
        if (prop[t] != 0.0f)
            push_entry(pi[t], pj[t], pj[t], prop[t] * scale, 0.0f);
    }
}

// ---------------------------------------------------------------------------
// Fused kernel: blocks [0, CONV_BLOCKS) convert x -> fp16;
//               blocks [CONV_BLOCKS, CONV_BLOCKS+WT_BLOCKS) compute weights.
// The two halves are independent; both must finish before row_scatter.
// ---------------------------------------------------------------------------
__global__ void __launch_bounds__(256)
prep_kernel(const float* __restrict__ x,
            const float* __restrict__ params,
            const int*   __restrict__ sampled)
{
    if (blockIdx.x < CONV_BLOCKS) {
        const int idx = blockIdx.x * 256 + threadIdx.x;     // float4 index
        if (idx >= IN_NUM_ * FEAT_ / 4) return;
        const float4 v = __ldg((const float4*)x + idx);
        __half2* dst = (__half2*)(g_xh + (size_t)idx * 4);
        dst[0] = __floats2half2_rn(v.x, v.y);
        dst[1] = __floats2half2_rn(v.z, v.w);
    } else {
        const int k = (blockIdx.x - CONV_BLOCKS) * 256 + threadIdx.x;
        if (k >= K_NUM) return;
        compute_edge(k, params, sampled);
    }
}

// ---------------------------------------------------------------------------
// Row gather: one warp per output row — fp16 gathers (256B/row), fp32
// accumulate, single plain STG per row. Overflow entries (never in practice)
// handled inline by scanning the overflow list.
// ---------------------------------------------------------------------------
__device__ __forceinline__ void acc_row_h(int j, float w, int lane,
                                          float& ax, float& ay,
                                          float& az, float& aw) {
    const uint2 rv = __ldg((const uint2*)(g_xh + (size_t)j * FEAT_) + lane);
    const float2 lo = __half22float2(*(const __half2*)&rv.x);
    const float2 hi = __half22float2(*(const __half2*)&rv.y);
    ax = fmaf(w, lo.x, ax);
    ay = fmaf(w, lo.y, ay);
    az = fmaf(w, hi.x, az);
    aw = fmaf(w, hi.y, aw);
}

__global__ void __launch_bounds__(256)
row_scatter_kernel(float* __restrict__ out)
{
    const int row  = (blockIdx.x * blockDim.x + threadIdx.x) >> 5;
    const int lane = threadIdx.x & 31;
    if (row >= OUT_NUM_) return;

    const int raw_n = g_cnt[row];
    const int n = min(raw_n, CAP);
    const float4* base = g_entry + (size_t)row * CAP;

    float ax = 0.0f, ay = 0.0f, az = 0.0f, aw = 0.0f;

    if (n > 0) {
        float4 rec = base[0];                       // warp-broadcast load
        for (int e = 0; e < n; e++) {
            const float4 nxt = (e + 1 < n) ? base[e + 1] : rec;  // prefetch
            acc_row_h(__float_as_int(rec.x), rec.z, lane, ax, ay, az, aw);
            if (rec.w != 0.0f)                      // warp-uniform branch
                acc_row_h(__float_as_int(rec.y), rec.w, lane, ax, ay, az, aw);
            rec = nxt;
        }
    }

    // Overflow path: engaged only if this row's bucket overflowed (P ~ 1e-25).
    if (raw_n > CAP) {
        const int ocnt = min(g_cnt[OUT_NUM_], OVF_CAP);
        for (int e = 0; e < ocnt; e++) {
            const float4 rec = g_ovf[e];
            if (__float_as_int(rec.x) == row)
                acc_row_h(__float_as_int(rec.y), rec.z, lane, ax, ay, az, aw);
        }
    }

    ((float4*)(out + (size_t)row * FEAT_))[lane] = make_float4(ax, ay, az, aw);
}

extern "C" void kernel_launch(void* const* d_in, const int* in_sizes, int n_in,
                              void* d_out, int out_size) {
    const float* params  = (const float*)d_in[0];   // (K, 4)
    const float* x       = (const float*)d_in[1];   // (IN_NUM, 128)
    const int*   sampled = (const int*)  d_in[2];   // (K, 12, 2)
    float*       out     = (float*)d_out;           // (OUT_NUM, 128)

    // Single memset zeroes bucket counters + overflow counter.
    void* cnt_addr = nullptr;
    cudaGetSymbolAddress(&cnt_addr, g_cnt);
    cudaMemsetAsync(cnt_addr, 0, (OUT_NUM_ + 1) * sizeof(int));

    prep_kernel<<<CONV_BLOCKS + WT_BLOCKS, 256>>>(x, params, sampled);
    row_scatter_kernel<<<(OUT_NUM_ * 32 + 255) / 256, 256>>>(out);
}

// round 16
// speedup vs baseline: 1.1657x; 1.0191x over previous
#include <cuda_runtime.h>
#include <cuda_bf16.h>
#include <cuda_fp16.h>
#include <cstdint>
#include <math.h>

// Problem constants (match reference)
#define K_NUM    131072
#define IN_NUM_  50000
#define OUT_NUM_ 50000
#define FEAT_    128
#define NPTS     16
#define ADD_     12
#define EPS_     1e-7f

// Per-output-row bucket capacity (Poisson(<=8.4) peak; overflow path guards).
#define CAP      40
#define OVF_CAP  65536

// Fused kernel block split
#define CONV_BLOCKS  ((IN_NUM_ * FEAT_ / 4 + 255) / 256)   // 6250
#define WT_BLOCKS    ((K_NUM + 255) / 256)                 // 512

// ---------------------------------------------------------------------------
// Bit-exact sigmoid path (DO NOT TOUCH — verified R10-R15).
// Cephes-classic f32 exp as XLA:CPU emits on aarch64 NEON (FMA pmadd).
// Needed ONLY for m0/m1 (discrete floor/ceil sensitivity).
// ---------------------------------------------------------------------------
__device__ __forceinline__ float cephes_expf_fma(float x) {
    const float LOG2EF = 1.44269504088896341f;
    const float C1     = 0.693359375f;
    const float C2     = -2.12194440e-4f;

    float fx = __fmaf_rn(x, LOG2EF, 0.5f);
    fx = floorf(fx);

    const float tmp = __fmul_rn(fx, C1);
    const float z   = __fmul_rn(fx, C2);
    float xr = __fsub_rn(x, tmp);
    xr = __fsub_rn(xr, z);

    const float zz = __fmul_rn(xr, xr);

    float y =             1.9875691500e-4f;
    y = __fmaf_rn(y, xr,  1.3981999507e-3f);
    y = __fmaf_rn(y, xr,  8.3334519073e-3f);
    y = __fmaf_rn(y, xr,  4.1665795894e-2f);
    y = __fmaf_rn(y, xr,  1.6666665459e-1f);
    y = __fmaf_rn(y, xr,  5.0000001201e-1f);
    y = __fmaf_rn(y, zz,  xr);
    y = __fadd_rn(y, 1.0f);

    const int n = (int)fx;
    const float p2n = __int_as_float((n + 127) << 23);
    return __fmul_rn(y, p2n);
}

__device__ __forceinline__ float sigmoid_ref(float v) {
    const float e = cephes_expf_fma(-v);
    return __fdiv_rn(1.0f, __fadd_rn(1.0f, e));
}

// Smooth-path sigmoid (value) — plain expf ample.
__device__ __forceinline__ float sigmoid_fast(float v) {
    return 1.0f / (1.0f + expf(-v));
}

// fp32 softplus (sigma sensitivity ~1e-5 << tolerance; verified R12+).
__device__ __forceinline__ float softplus_f32(float v) {
    return fmaxf(v, 0.0f) + log1pf(expf(-fabsf(v)));
}

// ---------------------------------------------------------------------------
// Scratch (static __device__ arrays — no allocation)
// g_cnt[OUT_NUM_] is the overflow counter -> single memset covers both.
// Record format: float4( as_float(off0), as_float(off1), w0, w1 )
//   off = j * 256 (byte offset into g_xh). w1==0 -> skip 2nd gather.
// ---------------------------------------------------------------------------
__device__ int    g_cnt[OUT_NUM_ + 1];
__device__ float4 g_entry[(size_t)OUT_NUM_ * CAP];   // 25.6 MB
__device__ float4 g_ovf[OVF_CAP];                    // (row, off, w, 0)
__device__ __half g_xh[(size_t)IN_NUM_ * FEAT_];     // fp16 copy of x, 12.8 MB

__device__ __forceinline__ void push_entry(int row, int off0, int off1,
                                           float w0, float w1) {
    const int pos = atomicAdd(&g_cnt[row], 1);
    if (pos < CAP) {
        g_entry[(size_t)row * CAP + pos] =
            make_float4(__int_as_float(off0), __int_as_float(off1), w0, w1);
    } else {
        int op = atomicAdd(&g_cnt[OUT_NUM_], 1);
        if (op < OVF_CAP)
            g_ovf[op] = make_float4(__int_as_float(row), __int_as_float(off0), w0, 0.0f);
        if (w1 != 0.0f) {
            op = atomicAdd(&g_cnt[OUT_NUM_], 1);
            if (op < OVF_CAP)
                g_ovf[op] = make_float4(__int_as_float(row), __int_as_float(off1), w1, 0.0f);
        }
    }
}

// ---------------------------------------------------------------------------
// Weight computation body (1 thread / edge)
// ---------------------------------------------------------------------------
__device__ __forceinline__ void compute_edge(int k,
                                             const float* __restrict__ params,
                                             const int*   __restrict__ sampled) {
    const float4 p = __ldg((const float4*)params + k);

    // Bit-exact sigmoids for means (discrete); fast for value (smooth).
    const float m0 = __fmul_rn(sigmoid_ref(p.x), (float)(OUT_NUM_ - 1));
    const float m1 = __fmul_rn(sigmoid_ref(p.y), (float)(IN_NUM_ - 1));
    const float sp    = softplus_f32(__fadd_rn(p.z, 2.0f));
    const float sigma = __fmul_rn(__fmul_rn(__fadd_rn(sp, EPS_),
                                            (float)OUT_NUM_), 0.2f);
    const float inv_var = __fdiv_rn(1.0f, __fadd_rn(EPS_, sigma));
    const float value   = sigmoid_fast(p.w);

    const float f0 = floorf(m0), c0 = ceilf(m0);
    const float f1 = floorf(m1), c1 = ceilf(m1);

    int   pi[NPTS], pj[NPTS];
    float prop[NPTS];

    // Neighbor order matches FLOOR_MASK: (T,T),(T,F),(F,T),(F,F), True->floor
    pi[0] = (int)f0; pj[0] = (int)f1;
    pi[1] = (int)f0; pj[1] = (int)c1;
    pi[2] = (int)c0; pj[2] = (int)f1;
    pi[3] = (int)c0; pj[3] = (int)c1;

    const int4* sp4 = (const int4*)(sampled + (size_t)k * (ADD_ * 2));
    #pragma unroll
    for (int q = 0; q < 6; q++) {
        const int4 v = __ldg(sp4 + q);
        pi[4 + q * 2]     = v.x;  pj[4 + q * 2]     = v.y;
        pi[4 + q * 2 + 1] = v.z;  pj[4 + q * 2 + 1] = v.w;
    }

    // Neighbor props: arg in [-2.1e-3, 0] -> quadratic exp (err ~1.4e-9).
    #pragma unroll
    for (int t = 0; t < 4; t++) {
        const float di = (float)pi[t] - m0;
        const float dj = (float)pj[t] - m1;
        const float arg = -0.5f * (di * di + dj * dj) * inv_var;
        prop[t] = 1.0f + arg * (1.0f + 0.5f * arg);
    }
    // Sampled props: expf underflows to exactly 0 below ~-103.97 (skip).
    #pragma unroll
    for (int t = 4; t < NPTS; t++) {
        const float di = (float)pi[t] - m0;
        const float dj = (float)pj[t] - m1;
        const float arg = -0.5f * (di * di + dj * dj) * inv_var;
        prop[t] = (arg < -104.0f) ? 0.0f : expf(arg);
    }

    float denom = 0.0f;
    #pragma unroll
    for (int t = 0; t < NPTS; t++)
        denom = __fadd_rn(denom, __fadd_rn(prop[t], EPS_));
    const float scale = __fdiv_rn(value, denom);

    // Fused neighbor records (byte offsets = j * FEAT_ * sizeof(half) = j<<8)
    const int i0 = pi[0], i1 = pi[2];
    const int o0 = pj[0] << 8, o1 = pj[1] << 8;
    push_entry(i0, o0, o1, prop[0] * scale, prop[1] * scale);
    push_entry(i1, o0, o1, prop[2] * scale, prop[3] * scale);

    // Nonzero sampled points (~0.4%): single-input records (w1 = 0)
    #pragma unroll
    for (int t = 4; t < NPTS; t++) {
        if (prop[t] != 0.0f)
            push_entry(pi[t], pj[t] << 8, pj[t] << 8, prop[t] * scale, 0.0f);
    }
}

// ---------------------------------------------------------------------------
// Fused prep kernel: convert x -> fp16 (blocks < CONV_BLOCKS) + weights.
// ---------------------------------------------------------------------------
__global__ void __launch_bounds__(256)
prep_kernel(const float* __restrict__ x,
            const float* __restrict__ params,
            const int*   __restrict__ sampled)
{
    if (blockIdx.x < CONV_BLOCKS) {
        const int idx = blockIdx.x * 256 + threadIdx.x;     // float4 index
        if (idx >= IN_NUM_ * FEAT_ / 4) return;
        const float4 v = __ldg((const float4*)x + idx);
        __half2* dst = (__half2*)(g_xh + (size_t)idx * 4);
        dst[0] = __floats2half2_rn(v.x, v.y);
        dst[1] = __floats2half2_rn(v.z, v.w);
    } else {
        const int k = (blockIdx.x - CONV_BLOCKS) * 256 + threadIdx.x;
        if (k >= K_NUM) return;
        compute_edge(k, params, sampled);
    }
}

// ---------------------------------------------------------------------------
// Row gather: one warp per output row. Lane-parallel record fetch (1 load),
// shfl broadcast, unrolled gather loop, fp32 accumulate, one STG per row.
// ---------------------------------------------------------------------------
__device__ __forceinline__ void acc_row_h(int off, float w, int lane,
                                          float& ax, float& ay,
                                          float& az, float& aw) {
    const uint2 rv = __ldg((const uint2*)((const char*)g_xh + off) + lane);
    const float2 lo = __half22float2(*(const __half2*)&rv.x);
    const float2 hi = __half22float2(*(const __half2*)&rv.y);
    ax = fmaf(w, lo.x, ax);
    ay = fmaf(w, lo.y, ay);
    az = fmaf(w, hi.x, az);
    aw = fmaf(w, hi.y, aw);
}

__global__ void __launch_bounds__(256)
row_scatter_kernel(float* __restrict__ out)
{
    const int row  = (blockIdx.x * blockDim.x + threadIdx.x) >> 5;
    const int lane = threadIdx.x & 31;
    if (row >= OUT_NUM_) return;

    const int raw_n = g_cnt[row];
    const int n = min(raw_n, CAP);
    const float4* base = g_entry + (size_t)row * CAP;

    // One fully-parallel load: lane e holds record e (e < min(n,32)).
    float4 myrec = make_float4(0.0f, 0.0f, 0.0f, 0.0f);
    if (lane < n) myrec = base[lane];

    float ax = 0.0f, ay = 0.0f, az = 0.0f, aw = 0.0f;

    const int n32 = min(n, 32);
    #pragma unroll 2
    for (int e = 0; e < n32; e++) {
        const int   o0 = __shfl_sync(0xffffffffu, __float_as_int(myrec.x), e);
        const int   o1 = __shfl_sync(0xffffffffu, __float_as_int(myrec.y), e);
        const float w0 = __shfl_sync(0xffffffffu, myrec.z, e);
        const float w1 = __shfl_sync(0xffffffffu, myrec.w, e);
        acc_row_h(o0, w0, lane, ax, ay, az, aw);
        if (w1 != 0.0f)                             // warp-uniform branch
            acc_row_h(o1, w1, lane, ax, ay, az, aw);
    }
    // Tail records 32..n-1 (essentially never)
    for (int e = 32; e < n; e++) {
        const float4 rec = base[e];
        acc_row_h(__float_as_int(rec.x), rec.z, lane, ax, ay, az, aw);
        if (rec.w != 0.0f)
            acc_row_h(__float_as_int(rec.y), rec.w, lane, ax, ay, az, aw);
    }

    // Overflow path (P ~ 1e-25 per row; correctness guard only).
    if (raw_n > CAP) {
        const int ocnt = min(g_cnt[OUT_NUM_], OVF_CAP);
        for (int e = 0; e < ocnt; e++) {
            const float4 rec = g_ovf[e];
            if (__float_as_int(rec.x) == row)
                acc_row_h(__float_as_int(rec.y), rec.z, lane, ax, ay, az, aw);
        }
    }

    ((float4*)(out + (size_t)row * FEAT_))[lane] = make_float4(ax, ay, az, aw);
}

extern "C" void kernel_launch(void* const* d_in, const int* in_sizes, int n_in,
                              void* d_out, int out_size) {
    const float* params  = (const float*)d_in[0];   // (K, 4)
    const float* x       = (const float*)d_in[1];   // (IN_NUM, 128)
    const int*   sampled = (const int*)  d_in[2];   // (K, 12, 2)
    float*       out     = (float*)d_out;           // (OUT_NUM, 128)

    // Single memset zeroes bucket counters + overflow counter.
    void* cnt_addr = nullptr;
    cudaGetSymbolAddress(&cnt_addr, g_cnt);
    cudaMemsetAsync(cnt_addr, 0, (OUT_NUM_ + 1) * sizeof(int));

    prep_kernel<<<CONV_BLOCKS + WT_BLOCKS, 256>>>(x, params, sampled);
    row_scatter_kernel<<<(OUT_NUM_ * 32 + 255) / 256, 256>>>(out);
}